// round 12
// baseline (speedup 1.0000x reference)
#include <cuda_runtime.h>
#include <cuda_bf16.h>

constexpr int B_ROWS  = 1024;
constexpr int L_COLS  = 4096;
constexpr int THREADS = 128;               // threads per row-block
constexpr int PER     = L_COLS / THREADS;  // 32 elements per thread
constexpr float INV_TAU = 1.0f / 0.85f;
constexpr float A_COEF  = 2.0f * INV_TAU;  // r = A*c/(k+T)

__device__ float g_row[B_ROWS];
__device__ unsigned int g_counter;   // zero-init; self-resetting

// 7 blocks/SM * 148 SM = 1036 >= 1024 -> single wave, 73-reg budget (no spills)
__global__ __launch_bounds__(THREADS, 7)
void divloss_fused_kernel(const float* __restrict__ p_in,
                          const int*   __restrict__ lab_in,
                          float*       __restrict__ out) {
    const int row  = blockIdx.x;
    const int t    = threadIdx.x;
    const int lane = t & 31;
    const int warp = t >> 5;          // 4 warps

    const int4*   lab = reinterpret_cast<const int4*>(lab_in + (size_t)row * L_COLS) + t * 8;
    const float4* pv  = reinterpret_cast<const float4*>(p_in  + (size_t)row * L_COLS) + t * 8;

    // ---- labels: 8x LDG.128, pack 32 labels -> one 32-bit mask ----
    int4 l0 = lab[0], l1 = lab[1], l2 = lab[2], l3 = lab[3];
    int4 l4 = lab[4], l5 = lab[5], l6 = lab[6], l7 = lab[7];

    unsigned bits = 0u;
    {
        const int4 ls[8] = { l0, l1, l2, l3, l4, l5, l6, l7 };
#pragma unroll
        for (int k = 0; k < 8; ++k) {
            bits |= ((unsigned)ls[k].x << (4 * k + 0))
                  | ((unsigned)ls[k].y << (4 * k + 1))
                  | ((unsigned)ls[k].z << (4 * k + 2))
                  | ((unsigned)ls[k].w << (4 * k + 3));
        }
    }
    const int local = __popc(bits);

    // ---- prefetch p chunk 0 while the scan runs ----
    float4 a0 = pv[0], a1 = pv[1];

    // ---- warp inclusive scan of per-thread label counts ----
    int x = local;
#pragma unroll
    for (int o = 1; o < 32; o <<= 1) {
        int y = __shfl_up_sync(0xffffffffu, x, o);
        if (lane >= o) x += y;
    }
    __shared__ int s_warp[4];
    if (lane == 31) s_warp[warp] = x;
    __syncthreads();   // the only pre-compute barrier

    // ---- raking: every thread reads the 4 warp sums ----
    int off = 0, tot = 0;
#pragma unroll
    for (int w = 0; w < 4; ++w) {
        int s = s_warp[w];
        tot += s;
        if (w < warp) off += s;
    }

    const float Tf  = (float)tot;
    float cf = (float)(off + (x - local));          // exclusive prefix count
    const float d0f = (float)(t * PER + 1) + Tf;    // first denominator

    // ---- 4 software-pipelined chunks of 8 elements ----
    float s1 = 0.0f, s2 = 0.0f;
#pragma unroll
    for (int c = 0; c < 4; ++c) {
        float4 b0, b1;
        if (c < 3) { b0 = pv[2 * c + 2]; b1 = pv[2 * c + 3]; }   // prefetch next

        float pc[8] = { a0.x, a0.y, a0.z, a0.w, a1.x, a1.y, a1.z, a1.w };
        const float dc = d0f + (float)(8 * c);

        if (dc >= 1024.0f) {
            // one RCP per chunk: 1/(dc+j) = invc*(1 - x + x^2), x = j*invc
            const float invc = __fdividef(1.0f, dc);
            const float bA   = A_COEF * invc;
#pragma unroll
            for (int j = 0; j < 8; ++j) {
                cf += ((bits >> (8 * c + j)) & 1u) ? 1.0f : 0.0f;
                float xi   = (float)j * invc;
                float corr = fmaf(xi, xi, 1.0f) - xi;
                float r    = (cf * corr) * bA;
                float e    = __expf(r);
                float lpv  = __logf(pc[j]);
                s1 += e;
                s2  = fmaf(e, r - lpv, s2);
            }
        } else {
            // rare small-denominator path: exact per-element divide
#pragma unroll
            for (int j = 0; j < 8; ++j) {
                cf += ((bits >> (8 * c + j)) & 1u) ? 1.0f : 0.0f;
                float r   = __fdividef(A_COEF * cf, dc + (float)j);
                float e   = __expf(r);
                float lpv = __logf(pc[j]);
                s1 += e;
                s2  = fmaf(e, r - lpv, s2);
            }
        }
        a0 = b0; a1 = b1;
    }

    // ---- block reduce (s1, s2) over 4 warps ----
#pragma unroll
    for (int o = 16; o; o >>= 1) {
        s1 += __shfl_down_sync(0xffffffffu, s1, o);
        s2 += __shfl_down_sync(0xffffffffu, s2, o);
    }
    __shared__ float r1[4], r2[4];
    if (lane == 0) { r1[warp] = s1; r2[warp] = s2; }
    __syncthreads();

    __shared__ bool s_last;
    if (t == 0) {
        float a1s = (r1[0] + r1[1]) + (r1[2] + r1[3]);
        float a2s = (r2[0] + r2[1]) + (r2[2] + r2[3]);
        g_row[row] = __fdividef(a2s, a1s) - __logf(a1s);
        __threadfence();
        unsigned done = atomicAdd(&g_counter, 1u);
        s_last = (done == (unsigned)(B_ROWS - 1));
    }
    __syncthreads();

    // ---- last block: deterministic final reduction of all 1024 rows ----
    if (s_last) {
        if (t == 0) g_counter = 0;   // reset for graph replay
        float v = 0.0f;
#pragma unroll
        for (int k = 0; k < 8; ++k) v += g_row[t + 128 * k];   // fixed order
#pragma unroll
        for (int o = 16; o; o >>= 1) v += __shfl_down_sync(0xffffffffu, v, o);
        __shared__ float sh[4];
        if (lane == 0) sh[warp] = v;
        __syncthreads();
        if (t == 0) {
            float w = (sh[0] + sh[1]) + (sh[2] + sh[3]);
            out[0] = w * (1.0f / (float)B_ROWS);
        }
    }
}

extern "C" void kernel_launch(void* const* d_in, const int* in_sizes, int n_in,
                              void* d_out, int out_size) {
    const float* p_in   = (const float*)d_in[0];   // output: (B, L, 1) float32
    const int*   labels = (const int*)  d_in[1];   // labels: (B, L) int32
    float*       out    = (float*)d_out;

    divloss_fused_kernel<<<B_ROWS, THREADS>>>(p_in, labels, out);
}

// round 13
// speedup vs baseline: 1.4636x; 1.4636x over previous
#include <cuda_runtime.h>
#include <cuda_bf16.h>

constexpr int B_ROWS  = 1024;
constexpr int L_COLS  = 4096;
constexpr int THREADS = 256;
constexpr int GRID    = 256;               // persistent blocks
constexpr int RPB     = B_ROWS / GRID;     // 4 rows per block
constexpr int PER     = L_COLS / THREADS;  // 16 elements per thread
constexpr float INV_TAU = 1.0f / 0.85f;
constexpr float A_COEF  = 2.0f * INV_TAU;  // r = A*c/(k+T)

// padded p staging buffer: f4 idx -> byte 16*idx + 16*(idx>>2)  (conflict-free LDS.128)
constexpr int PBUF_BYTES = (L_COLS / 4) * 16 + (L_COLS / 16) * 16;   // 20480

__device__ float g_row[B_ROWS];
__device__ unsigned int g_counter;   // zero-init; self-resetting

__device__ __forceinline__ unsigned s2u(const void* p) {
    return (unsigned)__cvta_generic_to_shared(p);
}

__global__ __launch_bounds__(THREADS)   // NO min-blocks: registers stay unconstrained
void divloss_persist_kernel(const float* __restrict__ p_in,
                            const int*   __restrict__ lab_in,
                            float*       __restrict__ out) {
    __shared__ __align__(16) char sbuf[2][PBUF_BYTES];   // 40 KB double buffer for p
    __shared__ int   s_warp[8];
    __shared__ float r1[8], r2[8];
    __shared__ bool  s_last;

    const int t    = threadIdx.x;
    const int lane = t & 31;
    const int warp = t >> 5;

    // ---- cp.async prefetch of one row of p into sbuf[buf] (no registers held) ----
    auto prefetch_p = [&](int row, int buf) {
        const char* gp = (const char*)(p_in + (size_t)row * L_COLS);
        unsigned sb = s2u(sbuf[buf]);
#pragma unroll
        for (int j = 0; j < 4; ++j) {
            int idx = t + j * THREADS;                       // coalesced gmem
            unsigned so = sb + idx * 16 + (idx >> 2) * 16;   // padded smem target
            asm volatile("cp.async.cg.shared.global [%0], [%1], 16;"
                         :: "r"(so), "l"(gp + (size_t)idx * 16));
        }
        asm volatile("cp.async.commit_group;");
    };

    // ---- prologue: labels(row0) -> regs, p(row0) -> sbuf[0] ----
    {
        const int4* gl = reinterpret_cast<const int4*>(
                             lab_in + (size_t)blockIdx.x * L_COLS) + t * 4;
        // fallthrough into loop with nl* live
        int4 nl0 = gl[0], nl1 = gl[1], nl2 = gl[2], nl3 = gl[3];
        prefetch_p(blockIdx.x, 0);

        for (int i = 0; i < RPB; ++i) {
            const int row = blockIdx.x + i * GRID;

            // pack current row's 16 labels -> bitmask (frees nl regs)
            unsigned bits =
                 (unsigned)nl0.x        | ((unsigned)nl0.y << 1)  | ((unsigned)nl0.z << 2)  | ((unsigned)nl0.w << 3)
              | ((unsigned)nl1.x << 4)  | ((unsigned)nl1.y << 5)  | ((unsigned)nl1.z << 6)  | ((unsigned)nl1.w << 7)
              | ((unsigned)nl2.x << 8)  | ((unsigned)nl2.y << 9)  | ((unsigned)nl2.z << 10) | ((unsigned)nl2.w << 11)
              | ((unsigned)nl3.x << 12) | ((unsigned)nl3.y << 13) | ((unsigned)nl3.z << 14) | ((unsigned)nl3.w << 15);

            // prefetch NEXT row: labels -> regs, p -> other buffer (overlaps this row's compute)
            if (i + 1 < RPB) {
                const int4* g2 = reinterpret_cast<const int4*>(
                                     lab_in + (size_t)(row + GRID) * L_COLS) + t * 4;
                nl0 = g2[0]; nl1 = g2[1]; nl2 = g2[2]; nl3 = g2[3];
                prefetch_p(row + GRID, (i + 1) & 1);
            }

            // ---- scan of label counts ----
            const int local = __popc(bits);
            int x = local;
#pragma unroll
            for (int o = 1; o < 32; o <<= 1) {
                int y = __shfl_up_sync(0xffffffffu, x, o);
                if (lane >= o) x += y;
            }
            if (lane == 31) s_warp[warp] = x;

            // wait for THIS row's p (leave next row's group in flight)
            if (i + 1 < RPB) asm volatile("cp.async.wait_group 1;");
            else             asm volatile("cp.async.wait_group 0;");
            __syncthreads();   // joins scan results + p-buffer readiness

            int off = 0, tot = 0;
#pragma unroll
            for (int w = 0; w < 8; ++w) {
                int s = s_warp[w];
                tot += s;
                if (w < warp) off += s;
            }

            const float Tf  = (float)tot;
            float cf = (float)(off + (x - local));
            const float d0f = (float)(t * PER + 1) + Tf;

            // ---- read p from conflict-free padded smem ----
            const char* sb = sbuf[i & 1];
            float4 q0 = *(const float4*)(sb + 80 * t + 0);
            float4 q1 = *(const float4*)(sb + 80 * t + 16);
            float4 q2 = *(const float4*)(sb + 80 * t + 32);
            float4 q3 = *(const float4*)(sb + 80 * t + 48);
            float pc[PER] = { q0.x, q0.y, q0.z, q0.w, q1.x, q1.y, q1.z, q1.w,
                              q2.x, q2.y, q2.z, q2.w, q3.x, q3.y, q3.z, q3.w };

            float s1 = 0.0f, s2 = 0.0f;
            if (d0f >= 1024.0f) {
#pragma unroll
                for (int c = 0; c < 2; ++c) {
                    const float dc   = d0f + (float)(8 * c);
                    const float invc = __fdividef(1.0f, dc);
                    const float bA   = A_COEF * invc;
#pragma unroll
                    for (int j = 0; j < 8; ++j) {
                        cf += ((bits >> (8 * c + j)) & 1u) ? 1.0f : 0.0f;
                        float xi   = (float)j * invc;
                        float corr = fmaf(xi, xi, 1.0f) - xi;   // 1 - x + x^2
                        float r    = (cf * corr) * bA;
                        float e    = __expf(r);
                        float lpv  = __logf(pc[8 * c + j]);
                        s1 += e;
                        s2  = fmaf(e, r - lpv, s2);
                    }
                }
            } else {
#pragma unroll
                for (int j = 0; j < PER; ++j) {
                    cf += ((bits >> j) & 1u) ? 1.0f : 0.0f;
                    float r   = __fdividef(A_COEF * cf, d0f + (float)j);
                    float e   = __expf(r);
                    float lpv = __logf(pc[j]);
                    s1 += e;
                    s2  = fmaf(e, r - lpv, s2);
                }
            }

            // ---- block reduce (s1, s2) ----
#pragma unroll
            for (int o = 16; o; o >>= 1) {
                s1 += __shfl_down_sync(0xffffffffu, s1, o);
                s2 += __shfl_down_sync(0xffffffffu, s2, o);
            }
            if (lane == 0) { r1[warp] = s1; r2[warp] = s2; }
            __syncthreads();   // also fences p-buffer reads before next overwrite
            if (t == 0) {
                float a1 = (r1[0] + r1[1]) + (r1[2] + r1[3])
                         + (r1[4] + r1[5]) + (r1[6] + r1[7]);
                float a2 = (r2[0] + r2[1]) + (r2[2] + r2[3])
                         + (r2[4] + r2[5]) + (r2[6] + r2[7]);
                g_row[row] = __fdividef(a2, a1) - __logf(a1);
            }
        }
    }

    // ---- completion protocol: last finished block does the final reduction ----
    if (t == 0) {
        __threadfence();
        unsigned done = atomicAdd(&g_counter, 1u);
        s_last = (done == (unsigned)(GRID - 1));
    }
    __syncthreads();

    if (s_last) {
        if (t == 0) g_counter = 0;   // reset for graph replay
        float v = (g_row[t] + g_row[t + 256]) + (g_row[t + 512] + g_row[t + 768]);
#pragma unroll
        for (int o = 16; o; o >>= 1) v += __shfl_down_sync(0xffffffffu, v, o);
        __shared__ float sh[8];
        if (lane == 0) sh[warp] = v;
        __syncthreads();
        if (t == 0) {
            float w = (sh[0] + sh[1]) + (sh[2] + sh[3])
                    + (sh[4] + sh[5]) + (sh[6] + sh[7]);
            out[0] = w * (1.0f / (float)B_ROWS);
        }
    }
}

extern "C" void kernel_launch(void* const* d_in, const int* in_sizes, int n_in,
                              void* d_out, int out_size) {
    const float* p_in   = (const float*)d_in[0];   // output: (B, L, 1) float32
    const int*   labels = (const int*)  d_in[1];   // labels: (B, L) int32
    float*       out    = (float*)d_out;

    divloss_persist_kernel<<<GRID, THREADS>>>(p_in, labels, out);
}

// round 14
// speedup vs baseline: 1.5899x; 1.0863x over previous
#include <cuda_runtime.h>
#include <cuda_bf16.h>

constexpr int B_ROWS  = 1024;
constexpr int L_COLS  = 4096;
constexpr int THREADS = 256;               // threads per row-block
constexpr int PER     = L_COLS / THREADS;  // 16 elements per thread
// A2 = (2/tau) * log2(e): folds tau and the base-2 conversion into one constant
constexpr float A2  = (2.0f / 0.85f) * 1.4426950408889634f;
constexpr float LN2 = 0.6931471805599453f;

__device__ float g_row[B_ROWS];
__device__ unsigned int g_counter;   // zero-init; self-resetting

__device__ __forceinline__ float f_rcp(float x) {
    float y; asm("rcp.approx.f32 %0, %1;" : "=f"(y) : "f"(x)); return y;
}
__device__ __forceinline__ float f_ex2(float x) {
    float y; asm("ex2.approx.f32 %0, %1;" : "=f"(y) : "f"(x)); return y;
}
__device__ __forceinline__ float f_lg2(float x) {
    float y; asm("lg2.approx.f32 %0, %1;" : "=f"(y) : "f"(x)); return y;
}

// natural occupancy: no min-blocks cap (register squeezes regressed twice)
__global__ __launch_bounds__(THREADS)
void divloss_fused_kernel(const float* __restrict__ p_in,
                          const int*   __restrict__ lab_in,
                          float*       __restrict__ out) {
    const int row  = blockIdx.x;
    const int t    = threadIdx.x;
    const int lane = t & 31;
    const int warp = t >> 5;

    const int4*   lab = reinterpret_cast<const int4*>(lab_in + (size_t)row * L_COLS) + t * 4;
    const float4* pv  = reinterpret_cast<const float4*>(p_in  + (size_t)row * L_COLS) + t * 4;

    // ---- front-batched loads (8x LDG.128, MLP=8) ----
    int4   l0 = lab[0], l1 = lab[1], l2 = lab[2], l3 = lab[3];
    float4 p0 = pv[0],  p1 = pv[1],  p2 = pv[2],  p3 = pv[3];

    int lv[PER] = { l0.x, l0.y, l0.z, l0.w, l1.x, l1.y, l1.z, l1.w,
                    l2.x, l2.y, l2.z, l2.w, l3.x, l3.y, l3.z, l3.w };

    // per-thread label total: plain IADD chain (ALU pipe)
    int local = 0;
#pragma unroll
    for (int i = 0; i < PER; ++i) local += lv[i];

    // ---- warp inclusive scan of per-thread counts ----
    int x = local;
#pragma unroll
    for (int o = 1; o < 32; o <<= 1) {
        int y = __shfl_up_sync(0xffffffffu, x, o);
        if (lane >= o) x += y;
    }
    __shared__ int s_warp[8];
    if (lane == 31) s_warp[warp] = x;

    // ---- hoisted: lg2(p) now, overlapping the scan barrier (1 MUFU each) ----
    float g[PER] = { p0.x, p0.y, p0.z, p0.w, p1.x, p1.y, p1.z, p1.w,
                     p2.x, p2.y, p2.z, p2.w, p3.x, p3.y, p3.z, p3.w };
#pragma unroll
    for (int i = 0; i < PER; ++i) g[i] = f_lg2(g[i]);

    __syncthreads();   // the only pre-compute barrier

    // ---- raking: every thread reads the 8 warp sums ----
    int off = 0, tot = 0;
#pragma unroll
    for (int w = 0; w < 8; ++w) {
        int s = s_warp[w];
        tot += s;
        if (w < warp) off += s;
    }

    // A2c = A2 * (exclusive prefix count); d0f = k_first + T
    float A2c = A2 * (float)(off + (x - local));
    const float d0f = (float)(t * PER + 1 + tot);

    // ---- lean main loop: 10 instrs/element (3 MUFU, 6 FMA-pipe, 1 ALU) ----
    float s1 = 0.0f, s2 = 0.0f;
#pragma unroll
    for (int j = 0; j < PER; ++j) {
        // fj = 0.0f or 1.0f via one IMAD (ALU pipe) + reinterpret
        float fj = __int_as_float(lv[j] * 0x3F800000);
        A2c = fmaf(fj, A2, A2c);            // A2 * inclusive count
        float dk  = d0f + (float)j;         // FADD with immediate
        float u   = A2c * f_rcp(dk);        // u = r * log2e
        float e   = f_ex2(u);               // exp(r)
        s2 = fmaf(e, u - g[j], s2);         // e * (u - lg2 p)
        s1 += e;
    }

    // ---- block reduce (s1, s2) over 8 warps ----
#pragma unroll
    for (int o = 16; o; o >>= 1) {
        s1 += __shfl_down_sync(0xffffffffu, s1, o);
        s2 += __shfl_down_sync(0xffffffffu, s2, o);
    }
    __shared__ float r1[8], r2[8];
    if (lane == 0) { r1[warp] = s1; r2[warp] = s2; }
    __syncthreads();

    __shared__ bool s_last;
    if (t == 0) {
        float a1 = (r1[0] + r1[1]) + (r1[2] + r1[3])
                 + (r1[4] + r1[5]) + (r1[6] + r1[7]);
        float a2 = (r2[0] + r2[1]) + (r2[2] + r2[3])
                 + (r2[4] + r2[5]) + (r2[6] + r2[7]);
        // row = ln2 * (S2'/S1 - lg2(S1))
        g_row[row] = (__fdividef(a2, a1) - f_lg2(a1)) * LN2;
        __threadfence();
        unsigned done = atomicAdd(&g_counter, 1u);
        s_last = (done == (unsigned)(B_ROWS - 1));
    }
    __syncthreads();

    // ---- last block: deterministic final reduction of all 1024 rows ----
    if (s_last) {
        if (t == 0) g_counter = 0;   // reset for graph replay
        float v = (g_row[t] + g_row[t + 256]) + (g_row[t + 512] + g_row[t + 768]);
#pragma unroll
        for (int o = 16; o; o >>= 1) v += __shfl_down_sync(0xffffffffu, v, o);
        __shared__ float sh[8];
        if (lane == 0) sh[warp] = v;
        __syncthreads();
        if (t == 0) {
            float w = (sh[0] + sh[1]) + (sh[2] + sh[3])
                    + (sh[4] + sh[5]) + (sh[6] + sh[7]);
            out[0] = w * (1.0f / (float)B_ROWS);
        }
    }
}

extern "C" void kernel_launch(void* const* d_in, const int* in_sizes, int n_in,
                              void* d_out, int out_size) {
    const float* p_in   = (const float*)d_in[0];   // output: (B, L, 1) float32
    const int*   labels = (const int*)  d_in[1];   // labels: (B, L) int32
    float*       out    = (float*)d_out;

    divloss_fused_kernel<<<B_ROWS, THREADS>>>(p_in, labels, out);
}